// round 5
// baseline (speedup 1.0000x reference)
#include <cuda_runtime.h>

#define B_   16
#define N_   1024
#define H_   224
#define W_   224
#define W4   56               // W_/4
#define KS   23
#define HALF 11
#define SIGMA2X2 18.0f        // 2 * 3.0^2
#define RPB  32               // output rows per block
#define TILES_Y (H_ / RPB)    // 7
#define STRIP (RPB + KS - 1)  // 54 hist rows per strip
#define RT   8                // y-conv rows per unit -> (32/8)*56 = 224 units
#define XT   7                // x-conv cols per unit -> 32 tiles * 32 rows = 1024 units
#define XTILES (W_ / XT)      // 32
#define NTHR 256
#define NBLK (B_ * TILES_Y)   // 112 blocks — one per SM, single wave

#define HIST_F (STRIP * W_)   // 12096 floats
#define B_F    (RPB * W_)     // 7168 floats
#define SMEM_BYTES ((HIST_F + B_F) * (int)sizeof(float))  // 77056 B

__global__ void __launch_bounds__(NTHR, 1)
saliency_hist_kernel(const float* __restrict__ points, float* __restrict__ out) {
    extern __shared__ float smem[];
    float* s_hist = smem;            // [STRIP][W_]  point-count histogram
    float* s_B    = smem + HIST_F;   // [RPB][W_]    y-convolved
    __shared__ float s_w[KS];

    const int tidx = threadIdx.x;
    const int b    = blockIdx.x / TILES_Y;
    const int tile = blockIdx.x % TILES_Y;
    const int r0   = tile * RPB;
    const int ylo  = r0 - HALF;      // hist row 0 == global row ylo

    // ---- Phase 0: zero hist + normalized 1-D Gaussian ----
    {
        float4 z = make_float4(0.f, 0.f, 0.f, 0.f);
        float4* h4 = reinterpret_cast<float4*>(s_hist);
        #pragma unroll
        for (int k = tidx; k < HIST_F / 4; k += NTHR)
            h4[k] = z;
    }
    if (tidx < 32) {
        float d = (float)tidx - (float)(KS - 1) * 0.5f;
        float v = (tidx < KS) ? expf(-(d * d) / SIGMA2X2) : 0.0f;
        float s = v;
        #pragma unroll
        for (int off = 16; off > 0; off >>= 1)
            s += __shfl_xor_sync(0xFFFFFFFFu, s, off);
        if (tidx < KS) s_w[tidx] = v / s;
    }
    __syncthreads();

    // ---- Phase 1: histogram scatter — one smem atomic per matching point ----
    {
        const float2* pts = reinterpret_cast<const float2*>(points) + b * N_;
        #pragma unroll
        for (int i = tidx; i < N_; i += NTHR) {
            float2 p = pts[i];
            int x = (int)(p.x * (float)W_);   // truncation == astype(int32), nonneg
            int y = (int)(p.y * (float)H_);
            int u = y - ylo;
            if ((unsigned)u < (unsigned)STRIP &&
                (unsigned)x < (unsigned)W_ && (unsigned)y < (unsigned)H_)
                atomicAdd(&s_hist[u * W_ + x], 1.0f);
        }
    }
    __syncthreads();

    // ---- Phase 2: dense y-conv  B[rl][c] = sum_j w[j] * hist[rl+j][c] ----
    if (tidx < (RPB / RT) * W4) {             // 224 units, float4 columns
        int c4  = tidx % W4;
        int rl0 = (tidx / W4) * RT;

        float w[KS];
        #pragma unroll
        for (int j = 0; j < KS; j++) w[j] = s_w[j];

        float4 acc[RT];
        #pragma unroll
        for (int k = 0; k < RT; k++) acc[k] = make_float4(0.f, 0.f, 0.f, 0.f);

        const float4* hc = reinterpret_cast<const float4*>(s_hist) + c4;
        #pragma unroll
        for (int u = 0; u < RT + KS - 1; u++) {   // 30 strip rows
            float4 v = hc[(rl0 + u) * W4];
            #pragma unroll
            for (int k = 0; k < RT; k++) {
                int j = u - k;                    // compile-time per (u,k)
                if (j >= 0 && j < KS) {
                    acc[k].x = fmaf(w[j], v.x, acc[k].x);
                    acc[k].y = fmaf(w[j], v.y, acc[k].y);
                    acc[k].z = fmaf(w[j], v.z, acc[k].z);
                    acc[k].w = fmaf(w[j], v.w, acc[k].w);
                }
            }
        }
        float4* bc = reinterpret_cast<float4*>(s_B) + c4;
        #pragma unroll
        for (int k = 0; k < RT; k++)
            bc[(rl0 + k) * W4] = acc[k];
    }
    __syncthreads();

    // ---- Phase 3: dense x-conv, conflict-free (lane stride 7, gcd(7,32)=1) ----
    // units: (r, ct) with ct = unit % 32 -> warp lanes span 32 distinct banks.
    {
        float w[KS];
        #pragma unroll
        for (int j = 0; j < KS; j++) w[j] = s_w[j];

        #pragma unroll
        for (int it = 0; it < (RPB * XTILES) / NTHR; it++) {  // 4 iterations
            int unit = tidx + it * NTHR;
            int ct = unit % XTILES;
            int r  = unit / XTILES;
            int c0 = ct * XT;

            float acc[XT];
            #pragma unroll
            for (int k = 0; k < XT; k++) acc[k] = 0.f;

            const float* brow = s_B + r * W_;
            #pragma unroll
            for (int u = 0; u < XT + KS - 1; u++) {   // 29 taps window
                int cc = c0 - HALF + u;
                float v = ((unsigned)cc < (unsigned)W_) ? brow[cc] : 0.f;
                #pragma unroll
                for (int k = 0; k < XT; k++) {
                    int j = u - k;
                    if (j >= 0 && j < KS)
                        acc[k] = fmaf(w[j], v, acc[k]);
                }
            }

            float* orow = out + (b * H_ + r0 + r) * W_ + c0;
            #pragma unroll
            for (int k = 0; k < XT; k++)
                orow[k] = acc[k];
        }
    }
}

extern "C" void kernel_launch(void* const* d_in, const int* in_sizes, int n_in,
                              void* d_out, int out_size) {
    const float* points = (const float*)d_in[1];  // d_in[0] = feature_map (unused)
    float* out = (float*)d_out;
    cudaFuncSetAttribute(saliency_hist_kernel,
                         cudaFuncAttributeMaxDynamicSharedMemorySize, SMEM_BYTES);
    saliency_hist_kernel<<<NBLK, NTHR, SMEM_BYTES>>>(points, out);
}